// round 16
// baseline (speedup 1.0000x reference)
#include <cuda_runtime.h>
#include <math.h>

#define B_  32
#define C_  3
#define H_  480
#define W_  480
#define AH  30
#define AW  30
#define PAD 48          // int(0.1 * 480)

#define BROWS 30        // rows per blend block -> 16 groups -> 1536 blocks
#define NGROUPS (H_ / BROWS)
#define QW   (W_ / 4)   // 120 float4 pixels per row

#define WLO 0.03125f    // wx/wy at segment-start candidate (exact in fp32)
#define WHI 0.96875f    // wx/wy at segment-end candidate

// ---------------------------------------------------------------------------
// Single fused kernel: each block computes its batch's bbox from the 30x30
// attention map via candidate scan (exact: bilinear is linear between knots,
// so per-row/col maxima over the fine grid occur at 60 candidate positions),
// then runs the blend for its (b, c, 30-row group). No inter-block comms.
// ---------------------------------------------------------------------------
__global__ void __launch_bounds__(128) fused_kernel(const float* __restrict__ images,
                                                    const float* __restrict__ atten,
                                                    float* __restrict__ out) {
    __shared__ float s_att[AH * AW];
    __shared__ float s_q[60][AW];           // y-lerped rows at 60 h-candidates
    __shared__ float s_wmax[4];
    __shared__ int s_minh, s_maxh, s_minw, s_maxw;
    __shared__ __align__(16) float s_row[2][484];

    const int blk = blockIdx.x;             // (b, c, rowgroup)
    const int b   = blk / (C_ * NGROUPS);
    const int rem = blk - b * (C_ * NGROUPS);
    const int c   = rem / NGROUPS;
    const int y_base = (rem - c * NGROUPS) * BROWS;
    const int tid = threadIdx.x;

    // ---------------- load map + theta reduce ----------------
    const float* a = atten + b * (AH * AW);
    float m = -1e30f;
    for (int i = tid; i < AH * AW; i += 128) {
        float v = a[i];
        s_att[i] = v;
        m = fmaxf(m, v);
    }
#pragma unroll
    for (int s = 16; s > 0; s >>= 1)
        m = fmaxf(m, __shfl_xor_sync(0xffffffffu, m, s));
    if ((tid & 31) == 0) s_wmax[tid >> 5] = m;
    if (tid == 0) { s_minh = H_; s_maxh = -1; s_minw = W_; s_maxw = -1; }
    __syncthreads();
    const float theta = 0.5f * fmaxf(fmaxf(s_wmax[0], s_wmax[1]),
                                     fmaxf(s_wmax[2], s_wmax[3]));

    // ---------------- build Q: y-lerped rows at h-candidates ----------------
    // j=0: row 0 (top clamp region); j=59: row 29 (bottom); j=1..58: pairs
    // (k, WLO), (k, WHI) for k=0..28 -- reference order: y-lerp of coarse rows.
    for (int idx = tid; idx < 60 * AW; idx += 128) {
        const int j = idx / AW;
        const int x = idx - j * AW;
        float v;
        if (j == 0)       v = s_att[x];
        else if (j == 59) v = s_att[29 * AW + x];
        else {
            const int   k  = (j - 1) >> 1;
            const float wy = ((j - 1) & 1) ? WHI : WLO;
            v = s_att[k * AW + x] * (1.0f - wy) + s_att[(k + 1) * AW + x] * wy;
        }
        s_q[j][x] = v;
    }
    __syncthreads();

    // ---------------- row scan: minh/maxh ----------------
    {
        int minh = H_, maxh = -1;
        for (int h = tid; h < H_; h += 128) {
            float sy = (h + 0.5f) * 0.0625f - 0.5f;
            sy = fminf(fmaxf(sy, 0.0f), (float)(AH - 1));
            const int   y0 = (int)sy;
            const float wy = sy - (float)y0;
            const int   y1 = min(y0 + 1, AH - 1);
            const float* r0p = s_att + y0 * AW;
            const float* r1p = s_att + y1 * AW;

            float cprev = r0p[0] * (1.0f - wy) + r1p[0] * wy;   // colv[0]
            float mx = cprev;                                   // left clamp region
#pragma unroll 1
            for (int k = 0; k < AW - 1; ++k) {
                const float cnext = r0p[k + 1] * (1.0f - wy) + r1p[k + 1] * wy;
                const float e1 = cprev * (1.0f - WLO) + cnext * WLO;
                const float e2 = cprev * (1.0f - WHI) + cnext * WHI;
                mx = fmaxf(mx, fmaxf(e1, e2));
                cprev = cnext;
            }
            mx = fmaxf(mx, cprev);                              // right clamp region
            if (mx >= theta) { minh = min(minh, h); maxh = max(maxh, h); }
        }
        atomicMin(&s_minh, minh); atomicMax(&s_maxh, maxh);
    }

    // ---------------- col scan: minw/maxw ----------------
    {
        int minw = W_, maxw = -1;
        for (int w = tid; w < W_; w += 128) {
            float sx = (w + 0.5f) * 0.0625f - 0.5f;
            sx = fminf(fmaxf(sx, 0.0f), (float)(AW - 1));
            const int   x0 = (int)sx;
            const float wx = sx - (float)x0;
            const int   x1 = min(x0 + 1, AW - 1);
            const float omwx = 1.0f - wx;

            float mx = -1e30f;
#pragma unroll 1
            for (int j = 0; j < 60; ++j)
                mx = fmaxf(mx, s_q[j][x0] * omwx + s_q[j][x1] * wx);
            if (mx >= theta) { minw = min(minw, w); maxw = max(maxw, w); }
        }
        atomicMin(&s_minw, minw); atomicMax(&s_maxw, maxw);
    }
    __syncthreads();

    // ---------------- blend (R11 body, 30 rows) ----------------
    const int h0 = max(s_minh - PAD, 0);
    const int h1 = min(s_maxh + PAD, H_);
    const int w0 = max(s_minw - PAD, 0);
    const int w1 = min(s_maxw + PAD, W_);

    const int   crop_h = h1 - h0;
    const int   crop_w = w1 - w0;
    const float chf = (float)crop_h;
    const float cwf = (float)crop_w;
    const float sy_scale = chf * (1.0f / (float)H_);
    const float sx_scale = cwf * (1.0f / (float)W_);

    const int w0a = w0 & ~3;                    // float4-aligned window start
    const int off = w0 - w0a;
    const int nq  = ((w1 - w0a) + 3) >> 2;      // quads to fill (<= 121)

    int   fxa[4], fxb[4];
    float wxv[4];
    const int x_base = tid * 4;
    if (tid < QW) {
#pragma unroll
        for (int k = 0; k < 4; ++k) {
            float sx = ((float)(x_base + k) + 0.5f) * sx_scale - 0.5f;
            sx = fminf(fmaxf(sx, 0.0f), cwf - 1.0f);
            const int fx0 = (int)sx;
            wxv[k] = sx - (float)fx0;
            fxa[k] = off + fx0;
            fxb[k] = off + min(fx0 + 1, crop_w - 1);
        }
    }

    const float* __restrict__ imgc = images + ((size_t)(b * C_ + c)) * (H_ * W_);
    float* __restrict__ outc       = out    + ((size_t)(b * C_ + c)) * (H_ * W_);

#pragma unroll 1
    for (int r = 0; r < BROWS; ++r) {
        const int y = y_base + r;
        float* buf = s_row[r & 1];

        float sy = ((float)y + 0.5f) * sy_scale - 0.5f;
        sy = fminf(fmaxf(sy, 0.0f), chf - 1.0f);
        const int   fy0  = (int)sy;
        const float wy   = sy - (float)fy0;
        const float omwy = 1.0f - wy;
        const size_t r0  = (size_t)(h0 + fy0) * W_ + w0a;
        const size_t r1  = (size_t)(h0 + min(fy0 + 1, crop_h - 1)) * W_ + w0a;

        if (tid < nq) {
            const float4 a0 = *reinterpret_cast<const float4*>(imgc + r0 + 4 * tid);
            const float4 a1 = *reinterpret_cast<const float4*>(imgc + r1 + 4 * tid);
            float4 v;
            v.x = a0.x * omwy + a1.x * wy;
            v.y = a0.y * omwy + a1.y * wy;
            v.z = a0.z * omwy + a1.z * wy;
            v.w = a0.w * omwy + a1.w * wy;
            *reinterpret_cast<float4*>(&buf[4 * tid]) = v;
        }

        float4 idv = make_float4(0.f, 0.f, 0.f, 0.f);
        if (tid < QW)
            idv = *reinterpret_cast<const float4*>(imgc + (size_t)y * W_ + x_base);

        __syncthreads();        // one barrier per row (double-buffered smem)

        if (tid < QW) {
            float4 o;
            o.x = idv.x * 0.6f + 0.4f * (buf[fxa[0]] * (1.0f - wxv[0]) + buf[fxb[0]] * wxv[0]);
            o.y = idv.y * 0.6f + 0.4f * (buf[fxa[1]] * (1.0f - wxv[1]) + buf[fxb[1]] * wxv[1]);
            o.z = idv.z * 0.6f + 0.4f * (buf[fxa[2]] * (1.0f - wxv[2]) + buf[fxb[2]] * wxv[2]);
            o.w = idv.w * 0.6f + 0.4f * (buf[fxa[3]] * (1.0f - wxv[3]) + buf[fxb[3]] * wxv[3]);
            *reinterpret_cast<float4*>(outc + (size_t)y * W_ + x_base) = o;
        }
    }
}

// ---------------------------------------------------------------------------
extern "C" void kernel_launch(void* const* d_in, const int* in_sizes, int n_in,
                              void* d_out, int out_size) {
    const float* images = (const float*)d_in[0];
    const float* atten  = (const float*)d_in[1];
    float* out = (float*)d_out;

    fused_kernel<<<B_ * C_ * NGROUPS, 128>>>(images, atten, out);
}

// round 17
// speedup vs baseline: 1.5684x; 1.5684x over previous
#include <cuda_runtime.h>
#include <math.h>

#define B_  32
#define C_  3
#define H_  480
#define W_  480
#define AH  30
#define AW  30
#define PAD 48          // int(0.1 * 480)

#define NSLICE 4        // bbox: 4 slices of 120 rows+cols per batch
#define SLICE_LEN (H_ / NSLICE)

#define BROWS 30        // rows per blend block -> 16 groups -> 1536 blocks
#define NGROUPS (H_ / BROWS)
#define QW   (W_ / 4)   // 120 float4 pixels per row

#define WLO 0.03125f    // wx/wy at segment candidates (exact in fp32)
#define WHI 0.96875f

// Encoded bbox accumulators, zero-init == "empty mask" defaults.
// [0] = H - minh, [1] = maxh + 1, [2] = W - minw, [3] = maxw + 1.
// atomicMax-combined -> idempotent across graph replays.
__device__ int g_enc[B_][4];

// ---------------------------------------------------------------------------
// Kernel A: candidate-scan bbox (validated in R16). grid=(NSLICE, B_), 256 thr.
// Per-row/col maxima of the bilinear upsample occur at 60 lerp-knot candidates,
// so each h (resp. w) needs only a 30 (resp. 60)-term scan over smem.
// ---------------------------------------------------------------------------
__global__ void __launch_bounds__(256) bbox_kernel(const float* __restrict__ atten) {
    const int b     = blockIdx.y;
    const int slice = blockIdx.x;
    const int tid   = threadIdx.x;

    __shared__ float s_att[AH * AW];
    __shared__ float s_q[60][AW];           // y-lerped rows at 60 h-candidates
    __shared__ float s_wmax[8];
    __shared__ int s_minh, s_maxh, s_minw, s_maxw;

    const float* a = atten + b * (AH * AW);
    float m = -1e30f;
    for (int i = tid; i < AH * AW; i += 256) {
        float v = a[i];
        s_att[i] = v;
        m = fmaxf(m, v);
    }
#pragma unroll
    for (int s = 16; s > 0; s >>= 1)
        m = fmaxf(m, __shfl_xor_sync(0xffffffffu, m, s));
    if ((tid & 31) == 0) s_wmax[tid >> 5] = m;
    if (tid == 0) { s_minh = H_; s_maxh = -1; s_minw = W_; s_maxw = -1; }
    __syncthreads();
    float mm = fmaxf(fmaxf(fmaxf(s_wmax[0], s_wmax[1]), fmaxf(s_wmax[2], s_wmax[3])),
                     fmaxf(fmaxf(s_wmax[4], s_wmax[5]), fmaxf(s_wmax[6], s_wmax[7])));
    const float theta = 0.5f * mm;

    // build Q (cooperative; 1800 elems)
    for (int idx = tid; idx < 60 * AW; idx += 256) {
        const int j = idx / AW;
        const int x = idx - j * AW;
        float v;
        if (j == 0)       v = s_att[x];
        else if (j == 59) v = s_att[29 * AW + x];
        else {
            const int   k  = (j - 1) >> 1;
            const float wy = ((j - 1) & 1) ? WHI : WLO;
            v = s_att[k * AW + x] * (1.0f - wy) + s_att[(k + 1) * AW + x] * wy;
        }
        s_q[j][x] = v;
    }
    __syncthreads();

    const int lo = slice * SLICE_LEN;

    // row scan: this slice's 120 h values (threads 0..119)
    {
        int minh = H_, maxh = -1;
        for (int h = lo + tid; h < lo + SLICE_LEN; h += 256) {
            float sy = (h + 0.5f) * 0.0625f - 0.5f;
            sy = fminf(fmaxf(sy, 0.0f), (float)(AH - 1));
            const int   y0 = (int)sy;
            const float wy = sy - (float)y0;
            const int   y1 = min(y0 + 1, AH - 1);
            const float* r0p = s_att + y0 * AW;
            const float* r1p = s_att + y1 * AW;

            float cprev = r0p[0] * (1.0f - wy) + r1p[0] * wy;
            float mx = cprev;
#pragma unroll 1
            for (int k = 0; k < AW - 1; ++k) {
                const float cnext = r0p[k + 1] * (1.0f - wy) + r1p[k + 1] * wy;
                mx = fmaxf(mx, fmaxf(cprev * (1.0f - WLO) + cnext * WLO,
                                     cprev * (1.0f - WHI) + cnext * WHI));
                cprev = cnext;
            }
            mx = fmaxf(mx, cprev);
            if (mx >= theta) { minh = min(minh, h); maxh = max(maxh, h); }
        }
        atomicMin(&s_minh, minh); atomicMax(&s_maxh, maxh);
    }

    // col scan: this slice's 120 w values
    {
        int minw = W_, maxw = -1;
        for (int w = lo + tid; w < lo + SLICE_LEN; w += 256) {
            float sx = (w + 0.5f) * 0.0625f - 0.5f;
            sx = fminf(fmaxf(sx, 0.0f), (float)(AW - 1));
            const int   x0 = (int)sx;
            const float wx = sx - (float)x0;
            const int   x1 = min(x0 + 1, AW - 1);
            const float omwx = 1.0f - wx;

            float mx = -1e30f;
#pragma unroll 1
            for (int j = 0; j < 60; ++j)
                mx = fmaxf(mx, s_q[j][x0] * omwx + s_q[j][x1] * wx);
            if (mx >= theta) { minw = min(minw, w); maxw = max(maxw, w); }
        }
        atomicMin(&s_minw, minw); atomicMax(&s_maxw, maxw);
    }
    __syncthreads();

    if (tid == 0 && s_maxh >= 0) {
        atomicMax(&g_enc[b][0], H_ - s_minh);
        atomicMax(&g_enc[b][1], s_maxh + 1);
        atomicMax(&g_enc[b][2], W_ - s_minw);
        atomicMax(&g_enc[b][3], s_maxw + 1);
    }

    asm volatile("griddepcontrol.launch_dependents;" ::: "memory");
}

// ---------------------------------------------------------------------------
// Kernel B: fused crop-resize + mixup blend (R11 body, best measured).
// One block per (b, c, 30-row group); 128 threads; 1536 blocks.
// ---------------------------------------------------------------------------
__global__ void __launch_bounds__(128) blend_kernel(const float* __restrict__ images,
                                                    float* __restrict__ out) {
    const int blk = blockIdx.x;                 // (b, c, rowgroup)
    const int b   = blk / (C_ * NGROUPS);
    const int rem = blk - b * (C_ * NGROUPS);
    const int c   = rem / NGROUPS;
    const int y_base = (rem - c * NGROUPS) * BROWS;
    const int tid = threadIdx.x;

    __shared__ __align__(16) float s_row[2][484];

    asm volatile("griddepcontrol.wait;" ::: "memory");

    // decode + pad + clamp bbox (once per block)
    const int minh = H_ - g_enc[b][0];
    const int maxh = g_enc[b][1] - 1;
    const int minw = W_ - g_enc[b][2];
    const int maxw = g_enc[b][3] - 1;
    const int h0 = max(minh - PAD, 0);
    const int h1 = min(maxh + PAD, H_);
    const int w0 = max(minw - PAD, 0);
    const int w1 = min(maxw + PAD, W_);

    const int   crop_h = h1 - h0;
    const int   crop_w = w1 - w0;
    const float chf = (float)crop_h;
    const float cwf = (float)crop_w;
    const float sy_scale = chf * (1.0f / (float)H_);
    const float sx_scale = cwf * (1.0f / (float)W_);

    const int w0a = w0 & ~3;                    // float4-aligned window start
    const int off = w0 - w0a;
    const int nq  = ((w1 - w0a) + 3) >> 2;      // quads to fill (<= 121)

    // per-thread x-mapping, computed ONCE, reused for all 30 rows
    int   fxa[4], fxb[4];
    float wxv[4];
    const int x_base = tid * 4;
    if (tid < QW) {
#pragma unroll
        for (int k = 0; k < 4; ++k) {
            float sx = ((float)(x_base + k) + 0.5f) * sx_scale - 0.5f;
            sx = fminf(fmaxf(sx, 0.0f), cwf - 1.0f);
            const int fx0 = (int)sx;
            wxv[k] = sx - (float)fx0;
            fxa[k] = off + fx0;
            fxb[k] = off + min(fx0 + 1, crop_w - 1);
        }
    }

    const float* __restrict__ imgc = images + ((size_t)(b * C_ + c)) * (H_ * W_);
    float* __restrict__ outc       = out    + ((size_t)(b * C_ + c)) * (H_ * W_);

#pragma unroll 1
    for (int r = 0; r < BROWS; ++r) {
        const int y = y_base + r;
        float* buf = s_row[r & 1];

        float sy = ((float)y + 0.5f) * sy_scale - 0.5f;
        sy = fminf(fmaxf(sy, 0.0f), chf - 1.0f);
        const int   fy0  = (int)sy;
        const float wy   = sy - (float)fy0;
        const float omwy = 1.0f - wy;
        const size_t r0  = (size_t)(h0 + fy0) * W_ + w0a;
        const size_t r1  = (size_t)(h0 + min(fy0 + 1, crop_h - 1)) * W_ + w0a;

        if (tid < nq) {
            const float4 a0 = *reinterpret_cast<const float4*>(imgc + r0 + 4 * tid);
            const float4 a1 = *reinterpret_cast<const float4*>(imgc + r1 + 4 * tid);
            float4 v;
            v.x = a0.x * omwy + a1.x * wy;
            v.y = a0.y * omwy + a1.y * wy;
            v.z = a0.z * omwy + a1.z * wy;
            v.w = a0.w * omwy + a1.w * wy;
            *reinterpret_cast<float4*>(&buf[4 * tid]) = v;
        }

        float4 idv = make_float4(0.f, 0.f, 0.f, 0.f);
        if (tid < QW)
            idv = *reinterpret_cast<const float4*>(imgc + (size_t)y * W_ + x_base);

        __syncthreads();        // one barrier per row (double-buffered smem)

        if (tid < QW) {
            float4 o;
            o.x = idv.x * 0.6f + 0.4f * (buf[fxa[0]] * (1.0f - wxv[0]) + buf[fxb[0]] * wxv[0]);
            o.y = idv.y * 0.6f + 0.4f * (buf[fxa[1]] * (1.0f - wxv[1]) + buf[fxb[1]] * wxv[1]);
            o.z = idv.z * 0.6f + 0.4f * (buf[fxa[2]] * (1.0f - wxv[2]) + buf[fxb[2]] * wxv[2]);
            o.w = idv.w * 0.6f + 0.4f * (buf[fxa[3]] * (1.0f - wxv[3]) + buf[fxb[3]] * wxv[3]);
            *reinterpret_cast<float4*>(outc + (size_t)y * W_ + x_base) = o;
        }
    }
}

// ---------------------------------------------------------------------------
extern "C" void kernel_launch(void* const* d_in, const int* in_sizes, int n_in,
                              void* d_out, int out_size) {
    const float* images = (const float*)d_in[0];
    const float* atten  = (const float*)d_in[1];
    float* out = (float*)d_out;

    bbox_kernel<<<dim3(NSLICE, B_), 256>>>(atten);

    cudaLaunchConfig_t cfg = {};
    cfg.gridDim  = dim3(B_ * C_ * NGROUPS);     // 1536 blocks
    cfg.blockDim = dim3(128);
    cfg.dynamicSmemBytes = 0;
    cfg.stream = 0;
    cudaLaunchAttribute attrs[1];
    attrs[0].id = cudaLaunchAttributeProgrammaticStreamSerialization;
    attrs[0].val.programmaticStreamSerializationAllowed = 1;
    cfg.attrs = attrs;
    cfg.numAttrs = 1;
    cudaLaunchKernelEx(&cfg, blend_kernel, images, out);
}